// round 13
// baseline (speedup 1.0000x reference)
#include <cuda_runtime.h>
#include <cuda_fp16.h>
#include <math.h>
#include <stdint.h>

#define NTH 128
#define BM 64
#define BN 64
#define NBH 32
#define SEQ 2048

// smem (per CTA, 96KB -> 2 CTAs/SM): K double-buffered (buf1 overlays the
// Q staging region, dead after Q-fragment preload); V fp16 double-buffered.
#define SM_K0HI 0
#define SM_K0LO 16384
#define SM_K1HI 32768
#define SM_K1LO 49152
#define SM_V0   65536
#define SM_V1   81920
#define SM_TOTAL 98304
#define SM_QHI SM_K1HI
#define SM_QLO SM_K1LO

#define NF4 (NBH * SEQ * 128 / 4)    // float4 count per tensor

// pre-split planes: K as bf16 hi/lo, V as fp16 (single plane)
__device__ __align__(16) uint2 gKhi[NF4];
__device__ __align__(16) uint2 gKlo[NF4];
__device__ __align__(16) uint2 gVh [NF4];

static __device__ __forceinline__ uint32_t s2u(const void* p) {
    return (uint32_t)__cvta_generic_to_shared((void*)p);
}

// split fp32 pair -> bf16x2 hi + bf16x2 lo (rn split; lo compensates hi)
static __device__ __forceinline__ void split2(float x, float y,
                                              uint32_t& hi, uint32_t& lo) {
    uint32_t h2;
    asm("cvt.rn.bf16x2.f32 %0, %1, %2;" : "=r"(h2) : "f"(y), "f"(x));
    float hx = __uint_as_float(h2 << 16);
    float hy = __uint_as_float(h2 & 0xffff0000u);
    float lx = x - hx, ly = y - hy;
    uint32_t l2;
    asm("cvt.rn.bf16x2.f32 %0, %1, %2;" : "=r"(l2) : "f"(ly), "f"(lx));
    hi = h2; lo = l2;
}

static __device__ __forceinline__ uint32_t packh2(float x, float y) {
    __half2 h = __float22half2_rn(make_float2(x, y));
    return *(uint32_t*)&h;
}

static __device__ __forceinline__ void ldsm4(uint32_t* r, uint32_t a) {
    asm volatile("ldmatrix.sync.aligned.m8n8.x4.shared.b16 {%0,%1,%2,%3}, [%4];"
                 : "=r"(r[0]), "=r"(r[1]), "=r"(r[2]), "=r"(r[3]) : "r"(a));
}
static __device__ __forceinline__ void ldsm4t(uint32_t* r, uint32_t a) {
    asm volatile("ldmatrix.sync.aligned.m8n8.x4.trans.shared.b16 {%0,%1,%2,%3}, [%4];"
                 : "=r"(r[0]), "=r"(r[1]), "=r"(r[2]), "=r"(r[3]) : "r"(a));
}

static __device__ __forceinline__ void mma16816(float* c, const uint32_t* a,
                                                uint32_t b0, uint32_t b1) {
    asm volatile(
        "mma.sync.aligned.m16n8k16.row.col.f32.bf16.bf16.f32 "
        "{%0,%1,%2,%3}, {%4,%5,%6,%7}, {%8,%9}, {%0,%1,%2,%3};"
        : "+f"(c[0]), "+f"(c[1]), "+f"(c[2]), "+f"(c[3])
        : "r"(a[0]), "r"(a[1]), "r"(a[2]), "r"(a[3]), "r"(b0), "r"(b1));
}

static __device__ __forceinline__ void mma16816h(float* c, const uint32_t* a,
                                                 uint32_t b0, uint32_t b1) {
    asm volatile(
        "mma.sync.aligned.m16n8k16.row.col.f32.f16.f16.f32 "
        "{%0,%1,%2,%3}, {%4,%5,%6,%7}, {%8,%9}, {%0,%1,%2,%3};"
        : "+f"(c[0]), "+f"(c[1]), "+f"(c[2]), "+f"(c[3])
        : "r"(a[0]), "r"(a[1]), "r"(a[2]), "r"(a[3]), "r"(b0), "r"(b1));
}

static __device__ __forceinline__ void cp16(uint32_t smem_dst, const void* gsrc) {
    asm volatile("cp.async.cg.shared.global [%0], [%1], 16;"
                 :: "r"(smem_dst), "l"(gsrc) : "memory");
}
static __device__ __forceinline__ void cp_commit() {
    asm volatile("cp.async.commit_group;" ::: "memory");
}
template <int N>
static __device__ __forceinline__ void cp_wait() {
    asm volatile("cp.async.wait_group %0;" :: "n"(N) : "memory");
}

// swizzled byte offset for (row, 16B-granule g, 8B half hb) in a 256B-row tile
static __device__ __forceinline__ uint32_t swz(int row, int g, int hb) {
    return (uint32_t)row * 256u + (uint32_t)((g ^ (row & 7)) << 4) + (uint32_t)hb * 8u;
}

// ---- pre-pass: split K (bf16 hi/lo) and V (fp16) once ----
__global__ __launch_bounds__(256, 8)
void presplit_kernel(const float* __restrict__ gk, const float* __restrict__ gv)
{
    int i = blockIdx.x * 256 + threadIdx.x;      // float4 index
    if (blockIdx.y == 0) {
        float4 x = ((const float4*)gk)[i];
        uint32_t h0, l0, h1, l1;
        split2(x.x, x.y, h0, l0);
        split2(x.z, x.w, h1, l1);
        gKhi[i] = make_uint2(h0, h1);
        gKlo[i] = make_uint2(l0, l1);
    } else {
        float4 x = ((const float4*)gv)[i];
        gVh[i] = make_uint2(packh2(x.x, x.y), packh2(x.z, x.w));
    }
}

__global__ __launch_bounds__(NTH, 2)
void fa_mma_kernel(const float* __restrict__ gq, float* __restrict__ go)
{
    extern __shared__ char smem[];
    const uint32_t sb = s2u(smem);
    const int tid = threadIdx.x;
    const int w   = tid >> 5, ln = tid & 31;
    const int grp = ln >> 2, tg = ln & 3;
    const int l15 = ln & 15, l16 = ln >> 4;
    const int qt  = (int)gridDim.x - 1 - (int)blockIdx.x;   // heavy CTAs first
    const int bh  = blockIdx.y;

    const float* qb = gq + ((size_t)bh * SEQ + (size_t)qt * BM) * 128;
    float*       ob = go + ((size_t)bh * SEQ + (size_t)qt * BM) * 128;
    const char* kbhi = (const char*)gKhi + (size_t)bh * SEQ * 256;
    const char* kblo = (const char*)gKlo + (size_t)bh * SEQ * 256;
    const char* vbh  = (const char*)gVh  + (size_t)bh * SEQ * 256;

    // ---- Q: load fp32, split to bf16 hi/lo into the K1 region (staging) ----
    #pragma unroll
    for (int i = 0; i < 16; i++) {
        int f = tid + i * NTH;               // float4 idx; row=f>>5, c4=f&31
        int r = f >> 5, c4 = f & 31;
        float4 qq = ((const float4*)qb)[f];
        uint32_t h0, l0, h1, l1;
        split2(qq.x, qq.y, h0, l0);
        split2(qq.z, qq.w, h1, l1);
        uint32_t off = swz(r, c4 >> 1, c4 & 1);
        *(uint2*)(smem + SM_QHI + off) = make_uint2(h0, h1);
        *(uint2*)(smem + SM_QLO + off) = make_uint2(l0, l1);
    }
    __syncthreads();

    const int nch = qt + 1;

    // ---- prefetch chunk 0 into buf0 (doesn't touch Q staging region) ----
    #pragma unroll
    for (int i = 0; i < 8; i++) {
        int f = tid + i * NTH;               // granule 0..1023
        int r = f >> 4, g = f & 15;
        uint32_t d = (uint32_t)r * 256u + (uint32_t)((g ^ (r & 7)) << 4);
        size_t s = (size_t)f * 16u;
        cp16(sb + SM_K0HI + d, kbhi + s);
        cp16(sb + SM_K0LO + d, kblo + s);
        cp16(sb + SM_V0   + d, vbh  + s);
    }
    cp_commit();

    // ---- Q fragments -> registers (held for the whole kernel) ----
    const int qr = w * 16 + l15;
    const uint32_t qbaseH = sb + SM_QHI + qr * 256;
    const uint32_t qbaseL = sb + SM_QLO + qr * 256;
    const int qx = qr & 7;
    uint32_t qhr[8][4], qlr[8][4];
    #pragma unroll
    for (int kb8 = 0; kb8 < 8; kb8++) {
        uint32_t goff = (uint32_t)(((kb8 * 2 + l16) ^ qx) << 4);
        ldsm4(qhr[kb8], qbaseH + goff);
        ldsm4(qlr[kb8], qbaseL + goff);
    }
    __syncthreads();                         // Q region dead -> usable as K1

    // ---- prefetch chunk min(1, qt) into buf1 (overlays old Q region) ----
    {
        int c1 = (qt >= 1) ? 1 : 0;
        size_t tb = (size_t)c1 * BN * 256;
        #pragma unroll
        for (int i = 0; i < 8; i++) {
            int f = tid + i * NTH;
            int r = f >> 4, g = f & 15;
            uint32_t d = (uint32_t)r * 256u + (uint32_t)((g ^ (r & 7)) << 4);
            size_t s = tb + (size_t)f * 16u;
            cp16(sb + SM_K1HI + d, kbhi + s);
            cp16(sb + SM_K1LO + d, kblo + s);
            cp16(sb + SM_V1   + d, vbh  + s);
        }
        cp_commit();
    }

    float o_[16][4];
    #pragma unroll
    for (int j = 0; j < 16; j++)
        #pragma unroll
        for (int e = 0; e < 4; e++) o_[j][e] = 0.f;
    float mA = -INFINITY, mB = -INFINITY, lA = 0.f, lB = 0.f;

    const int grow0 = qt * BM + w * 16 + grp;    // global q-row of c0/c1

    for (int c = 0; c < nch; c++) {
        const int buf = c & 1;
        const uint32_t kb = sb + (buf ? SM_K1HI : SM_K0HI);
        const uint32_t vb = sb + (buf ? SM_V1   : SM_V0);
        const bool diag = (c == qt);
        // diagonal chunk: warp w's rows (w*16..w*16+15) only need k-col
        // blocks [0, 16*(w+1)); blocks beyond are fully causal-masked.
        const int blkmax = diag ? (w + 1) : 4;

        cp_wait<1>();                        // chunk c landed (c+1 in flight)
        __syncthreads();

        // ---- S = Q K^T  (3-way bf16 split; skip fully-masked ntp blocks) ----
        float sc[8][4];
        #pragma unroll
        for (int j = 0; j < 8; j++)
            #pragma unroll
            for (int e = 0; e < 4; e++) sc[j][e] = 0.f;

        #pragma unroll
        for (int ntp = 0; ntp < 4; ntp++) {
            if (ntp >= blkmax) break;
            int kr = ntp * 16 + l15;
            #pragma unroll
            for (int kb8 = 0; kb8 < 8; kb8++) {
                uint32_t koff = swz(kr, kb8 * 2 + l16, 0);
                uint32_t kh[4], kl[4];
                ldsm4(kh, kb + koff);
                ldsm4(kl, kb + 16384 + koff);
                mma16816(sc[2 * ntp],     qhr[kb8], kh[0], kh[2]);
                mma16816(sc[2 * ntp],     qlr[kb8], kh[0], kh[2]);
                mma16816(sc[2 * ntp],     qhr[kb8], kl[0], kl[2]);
                mma16816(sc[2 * ntp + 1], qhr[kb8], kh[1], kh[3]);
                mma16816(sc[2 * ntp + 1], qlr[kb8], kh[1], kh[3]);
                mma16816(sc[2 * ntp + 1], qhr[kb8], kl[1], kl[3]);
            }
        }

        // ---- causal mask (all 8 n8-blocks; skipped blocks become -inf) ----
        if (diag) {
            #pragma unroll
            for (int j = 0; j < 8; j++) {
                int gcol = c * BN + j * 8 + tg * 2;
                if (gcol     > grow0)     sc[j][0] = -INFINITY;
                if (gcol + 1 > grow0)     sc[j][1] = -INFINITY;
                if (gcol     > grow0 + 8) sc[j][2] = -INFINITY;
                if (gcol + 1 > grow0 + 8) sc[j][3] = -INFINITY;
            }
        }

        // ---- row max + alpha (global over chunk; must precede exp) ----
        float mx0 = -INFINITY, mx1 = -INFINITY;
        #pragma unroll
        for (int j = 0; j < 8; j++) {
            mx0 = fmaxf(mx0, fmaxf(sc[j][0], sc[j][1]));
            mx1 = fmaxf(mx1, fmaxf(sc[j][2], sc[j][3]));
        }
        mx0 = fmaxf(mx0, __shfl_xor_sync(0xffffffffu, mx0, 1));
        mx0 = fmaxf(mx0, __shfl_xor_sync(0xffffffffu, mx0, 2));
        mx1 = fmaxf(mx1, __shfl_xor_sync(0xffffffffu, mx1, 1));
        mx1 = fmaxf(mx1, __shfl_xor_sync(0xffffffffu, mx1, 2));
        float mn0 = fmaxf(mA, mx0), mn1 = fmaxf(mB, mx1);
        float al0 = __expf(mA - mn0), al1 = __expf(mB - mn1);
        mA = mn0; mB = mn1;
        #pragma unroll
        for (int j = 0; j < 16; j++) {
            o_[j][0] *= al0; o_[j][1] *= al0;
            o_[j][2] *= al1; o_[j][3] *= al1;
        }

        // ---- interleaved exp + pack + PV per 16-row s-block ----
        float s0 = 0.f, s1 = 0.f;
        #pragma unroll
        for (int s = 0; s < 4; s++) {
            if (s >= blkmax) break;
            #pragma unroll
            for (int jj = 2 * s; jj <= 2 * s + 1; jj++) {
                sc[jj][0] = __expf(sc[jj][0] - mn0); s0 += sc[jj][0];
                sc[jj][1] = __expf(sc[jj][1] - mn0); s0 += sc[jj][1];
                sc[jj][2] = __expf(sc[jj][2] - mn1); s1 += sc[jj][2];
                sc[jj][3] = __expf(sc[jj][3] - mn1); s1 += sc[jj][3];
            }
            uint32_t ph[4];
            ph[0] = packh2(sc[2 * s][0],     sc[2 * s][1]);
            ph[1] = packh2(sc[2 * s][2],     sc[2 * s][3]);
            ph[2] = packh2(sc[2 * s + 1][0], sc[2 * s + 1][1]);
            ph[3] = packh2(sc[2 * s + 1][2], sc[2 * s + 1][3]);
            int vr = s * 16 + l15;
            #pragma unroll
            for (int dp = 0; dp < 8; dp++) {
                uint32_t voff = swz(vr, dp * 2 + l16, 0);
                uint32_t vh[4];
                ldsm4t(vh, vb + voff);
                mma16816h(o_[2 * dp],     ph, vh[0], vh[1]);
                mma16816h(o_[2 * dp + 1], ph, vh[2], vh[3]);
            }
        }

        // ---- l-sum reduction off the critical path (after PV issue) ----
        s0 += __shfl_xor_sync(0xffffffffu, s0, 1);
        s0 += __shfl_xor_sync(0xffffffffu, s0, 2);
        s1 += __shfl_xor_sync(0xffffffffu, s1, 1);
        s1 += __shfl_xor_sync(0xffffffffu, s1, 2);
        lA = lA * al0 + s0;
        lB = lB * al1 + s1;

        __syncthreads();                     // all warps done with buffers c&1

        // ---- prefetch chunk c+2 into this buffer (clamped on tail) ----
        {
            int cc = (c + 2 <= qt) ? c + 2 : qt;
            size_t tb = (size_t)cc * BN * 256;
            #pragma unroll
            for (int i = 0; i < 8; i++) {
                int f = tid + i * NTH;
                int r = f >> 4, g = f & 15;
                uint32_t d = (uint32_t)r * 256u + (uint32_t)((g ^ (r & 7)) << 4);
                size_t s = tb + (size_t)f * 16u;
                cp16(kb + d, kbhi + s);
                cp16(kb + 16384 + d, kblo + s);
                cp16(vb + d, vbh + s);
            }
            cp_commit();
        }
    }

    // ---- epilogue: normalize + store ----
    float inv0 = 1.0f / lA, inv1 = 1.0f / lB;
    float* r0 = ob + (size_t)(w * 16 + grp) * 128 + tg * 2;
    float* r1 = ob + (size_t)(w * 16 + grp + 8) * 128 + tg * 2;
    #pragma unroll
    for (int j = 0; j < 16; j++) {
        *(float2*)(r0 + j * 8) = make_float2(o_[j][0] * inv0, o_[j][1] * inv0);
        *(float2*)(r1 + j * 8) = make_float2(o_[j][2] * inv1, o_[j][3] * inv1);
    }
    cp_wait<0>();                            // drain trailing prefetches
}

extern "C" void kernel_launch(void* const* d_in, const int* in_sizes, int n_in,
                              void* d_out, int out_size) {
    const float* q = (const float*)d_in[0];
    const float* k = (const float*)d_in[1];
    const float* v = (const float*)d_in[2];
    // d_in[3]: causal tril mask — semantics implemented directly.
    float* out = (float*)d_out;

    dim3 pgrid(NF4 / 256, 2);
    presplit_kernel<<<pgrid, 256>>>(k, v);

    cudaFuncSetAttribute(fa_mma_kernel,
                         cudaFuncAttributeMaxDynamicSharedMemorySize, SM_TOTAL);
    dim3 grid(SEQ / BM, NBH);
    fa_mma_kernel<<<grid, NTH, SM_TOTAL>>>(q, out);
}

// round 14
// speedup vs baseline: 1.0495x; 1.0495x over previous
#include <cuda_runtime.h>
#include <cuda_fp16.h>
#include <math.h>
#include <stdint.h>

#define NTH 128
#define BM 64
#define BN 64
#define NBH 32
#define SEQ 2048

// smem (per CTA, 96KB -> 2 CTAs/SM): K double-buffered (buf1 overlays the
// Q staging region, dead after Q-fragment preload); V fp16 double-buffered.
#define SM_K0HI 0
#define SM_K0LO 16384
#define SM_K1HI 32768
#define SM_K1LO 49152
#define SM_V0   65536
#define SM_V1   81920
#define SM_TOTAL 98304
#define SM_QHI SM_K1HI
#define SM_QLO SM_K1LO

#define NF4 (NBH * SEQ * 128 / 4)    // float4 count per tensor

// pre-split planes: K as bf16 hi/lo, V as fp16 (single plane)
__device__ __align__(16) uint2 gKhi[NF4];
__device__ __align__(16) uint2 gKlo[NF4];
__device__ __align__(16) uint2 gVh [NF4];

static __device__ __forceinline__ uint32_t s2u(const void* p) {
    return (uint32_t)__cvta_generic_to_shared((void*)p);
}

// split fp32 pair -> bf16x2 hi + bf16x2 lo (rn split; lo compensates hi)
static __device__ __forceinline__ void split2(float x, float y,
                                              uint32_t& hi, uint32_t& lo) {
    uint32_t h2;
    asm("cvt.rn.bf16x2.f32 %0, %1, %2;" : "=r"(h2) : "f"(y), "f"(x));
    float hx = __uint_as_float(h2 << 16);
    float hy = __uint_as_float(h2 & 0xffff0000u);
    float lx = x - hx, ly = y - hy;
    uint32_t l2;
    asm("cvt.rn.bf16x2.f32 %0, %1, %2;" : "=r"(l2) : "f"(ly), "f"(lx));
    hi = h2; lo = l2;
}

static __device__ __forceinline__ uint32_t packh2(float x, float y) {
    __half2 h = __float22half2_rn(make_float2(x, y));
    return *(uint32_t*)&h;
}

static __device__ __forceinline__ void ldsm4(uint32_t* r, uint32_t a) {
    asm volatile("ldmatrix.sync.aligned.m8n8.x4.shared.b16 {%0,%1,%2,%3}, [%4];"
                 : "=r"(r[0]), "=r"(r[1]), "=r"(r[2]), "=r"(r[3]) : "r"(a));
}
static __device__ __forceinline__ void ldsm4t(uint32_t* r, uint32_t a) {
    asm volatile("ldmatrix.sync.aligned.m8n8.x4.trans.shared.b16 {%0,%1,%2,%3}, [%4];"
                 : "=r"(r[0]), "=r"(r[1]), "=r"(r[2]), "=r"(r[3]) : "r"(a));
}

static __device__ __forceinline__ void mma16816(float* c, const uint32_t* a,
                                                uint32_t b0, uint32_t b1) {
    asm volatile(
        "mma.sync.aligned.m16n8k16.row.col.f32.bf16.bf16.f32 "
        "{%0,%1,%2,%3}, {%4,%5,%6,%7}, {%8,%9}, {%0,%1,%2,%3};"
        : "+f"(c[0]), "+f"(c[1]), "+f"(c[2]), "+f"(c[3])
        : "r"(a[0]), "r"(a[1]), "r"(a[2]), "r"(a[3]), "r"(b0), "r"(b1));
}

static __device__ __forceinline__ void mma16816h(float* c, const uint32_t* a,
                                                 uint32_t b0, uint32_t b1) {
    asm volatile(
        "mma.sync.aligned.m16n8k16.row.col.f32.f16.f16.f32 "
        "{%0,%1,%2,%3}, {%4,%5,%6,%7}, {%8,%9}, {%0,%1,%2,%3};"
        : "+f"(c[0]), "+f"(c[1]), "+f"(c[2]), "+f"(c[3])
        : "r"(a[0]), "r"(a[1]), "r"(a[2]), "r"(a[3]), "r"(b0), "r"(b1));
}

static __device__ __forceinline__ void cp16(uint32_t smem_dst, const void* gsrc) {
    asm volatile("cp.async.cg.shared.global [%0], [%1], 16;"
                 :: "r"(smem_dst), "l"(gsrc) : "memory");
}
static __device__ __forceinline__ void cp_commit() {
    asm volatile("cp.async.commit_group;" ::: "memory");
}
template <int N>
static __device__ __forceinline__ void cp_wait() {
    asm volatile("cp.async.wait_group %0;" :: "n"(N) : "memory");
}

// swizzled byte offset for (row, 16B-granule g, 8B half hb) in a 256B-row tile
static __device__ __forceinline__ uint32_t swz(int row, int g, int hb) {
    return (uint32_t)row * 256u + (uint32_t)((g ^ (row & 7)) << 4) + (uint32_t)hb * 8u;
}

// ---- pre-pass: split K (bf16 hi/lo) and V (fp16) once ----
__global__ __launch_bounds__(256, 8)
void presplit_kernel(const float* __restrict__ gk, const float* __restrict__ gv)
{
    int i = blockIdx.x * 256 + threadIdx.x;      // float4 index
    if (blockIdx.y == 0) {
        float4 x = ((const float4*)gk)[i];
        uint32_t h0, l0, h1, l1;
        split2(x.x, x.y, h0, l0);
        split2(x.z, x.w, h1, l1);
        gKhi[i] = make_uint2(h0, h1);
        gKlo[i] = make_uint2(l0, l1);
    } else {
        float4 x = ((const float4*)gv)[i];
        gVh[i] = make_uint2(packh2(x.x, x.y), packh2(x.z, x.w));
    }
}

__global__ __launch_bounds__(NTH, 2)
void fa_mma_kernel(const float* __restrict__ gq, float* __restrict__ go)
{
    extern __shared__ char smem[];
    const uint32_t sb = s2u(smem);
    const int tid = threadIdx.x;
    const int w   = tid >> 5, ln = tid & 31;
    const int grp = ln >> 2, tg = ln & 3;
    const int l15 = ln & 15, l16 = ln >> 4;
    const int qt  = (int)gridDim.x - 1 - (int)blockIdx.x;   // heavy CTAs first
    const int bh  = blockIdx.y;

    const float* qb = gq + ((size_t)bh * SEQ + (size_t)qt * BM) * 128;
    float*       ob = go + ((size_t)bh * SEQ + (size_t)qt * BM) * 128;
    const char* kbhi = (const char*)gKhi + (size_t)bh * SEQ * 256;
    const char* kblo = (const char*)gKlo + (size_t)bh * SEQ * 256;
    const char* vbh  = (const char*)gVh  + (size_t)bh * SEQ * 256;

    // ---- Q: load fp32, split to bf16 hi/lo into the K1 region (staging) ----
    #pragma unroll
    for (int i = 0; i < 16; i++) {
        int f = tid + i * NTH;               // float4 idx; row=f>>5, c4=f&31
        int r = f >> 5, c4 = f & 31;
        float4 qq = ((const float4*)qb)[f];
        uint32_t h0, l0, h1, l1;
        split2(qq.x, qq.y, h0, l0);
        split2(qq.z, qq.w, h1, l1);
        uint32_t off = swz(r, c4 >> 1, c4 & 1);
        *(uint2*)(smem + SM_QHI + off) = make_uint2(h0, h1);
        *(uint2*)(smem + SM_QLO + off) = make_uint2(l0, l1);
    }
    __syncthreads();

    const int nch = qt + 1;

    // ---- prefetch chunk 0 into buf0 (doesn't touch Q staging region) ----
    #pragma unroll
    for (int i = 0; i < 8; i++) {
        int f = tid + i * NTH;               // granule 0..1023
        int r = f >> 4, g = f & 15;
        uint32_t d = (uint32_t)r * 256u + (uint32_t)((g ^ (r & 7)) << 4);
        size_t s = (size_t)f * 16u;
        cp16(sb + SM_K0HI + d, kbhi + s);
        cp16(sb + SM_K0LO + d, kblo + s);
        cp16(sb + SM_V0   + d, vbh  + s);
    }
    cp_commit();

    // ---- Q fragments -> registers (held for the whole kernel) ----
    const int qr = w * 16 + l15;
    const uint32_t qbaseH = sb + SM_QHI + qr * 256;
    const uint32_t qbaseL = sb + SM_QLO + qr * 256;
    const int qx = qr & 7;
    uint32_t qhr[8][4], qlr[8][4];
    #pragma unroll
    for (int kb8 = 0; kb8 < 8; kb8++) {
        uint32_t goff = (uint32_t)(((kb8 * 2 + l16) ^ qx) << 4);
        ldsm4(qhr[kb8], qbaseH + goff);
        ldsm4(qlr[kb8], qbaseL + goff);
    }
    __syncthreads();                         // Q region dead -> usable as K1

    float o_[16][4];
    #pragma unroll
    for (int j = 0; j < 16; j++)
        #pragma unroll
        for (int e = 0; e < 4; e++) o_[j][e] = 0.f;
    float mA = -INFINITY, mB = -INFINITY, lA = 0.f, lB = 0.f;

    const int grow0 = qt * BM + w * 16 + grp;    // global q-row of c0/c1

    for (int c = 0; c < nch; c++) {
        const int buf = c & 1;
        const uint32_t kb = sb + (buf ? SM_K1HI : SM_K0HI);
        const uint32_t vb = sb + (buf ? SM_V1   : SM_V0);

        cp_wait<0>();                        // chunk c landed
        __syncthreads();                     // visible to all; c-1 fully read

        // ---- prefetch chunk c+1 into the other buffer (free since c-1) ----
        if (c + 1 < nch) {
            const uint32_t kbn = sb + (buf ? SM_K0HI : SM_K1HI);
            const uint32_t vbn = sb + (buf ? SM_V0   : SM_V1);
            size_t tb = (size_t)(c + 1) * BN * 256;
            #pragma unroll
            for (int i = 0; i < 8; i++) {
                int f = tid + i * NTH;
                int r = f >> 4, g = f & 15;
                uint32_t d = (uint32_t)r * 256u + (uint32_t)((g ^ (r & 7)) << 4);
                size_t s = tb + (size_t)f * 16u;
                cp16(kbn + d, kbhi + s);
                cp16(kbn + 16384 + d, kblo + s);
                cp16(vbn + d, vbh + s);
            }
            cp_commit();
        }

        // ---- S = Q K^T  (3-way bf16 split; K frags ping-pong pipelined) ----
        float sc[8][4];
        #pragma unroll
        for (int j = 0; j < 8; j++)
            #pragma unroll
            for (int e = 0; e < 4; e++) sc[j][e] = 0.f;

        uint32_t kf[2][2][4];                // [pingpong][hi/lo][frag]
        {
            uint32_t koff0 = swz(l15, l16, 0);   // it=0: ntp=0, kb8=0
            ldsm4(kf[0][0], kb + koff0);
            ldsm4(kf[0][1], kb + 16384 + koff0);
        }
        #pragma unroll
        for (int it = 0; it < 32; it++) {    // it = kb8*4 + ntp
            const int cur = it & 1, nxt = cur ^ 1;
            if (it < 31) {
                const int it1 = it + 1;
                uint32_t koff = swz((it1 & 3) * 16 + l15,
                                    (it1 >> 2) * 2 + l16, 0);
                ldsm4(kf[nxt][0], kb + koff);
                ldsm4(kf[nxt][1], kb + 16384 + koff);
            }
            const int ntp = it & 3, kb8 = it >> 2;
            const uint32_t* kh = kf[cur][0];
            const uint32_t* kl = kf[cur][1];
            mma16816(sc[2 * ntp],     qhr[kb8], kh[0], kh[2]);
            mma16816(sc[2 * ntp],     qlr[kb8], kh[0], kh[2]);
            mma16816(sc[2 * ntp],     qhr[kb8], kl[0], kl[2]);
            mma16816(sc[2 * ntp + 1], qhr[kb8], kh[1], kh[3]);
            mma16816(sc[2 * ntp + 1], qlr[kb8], kh[1], kh[3]);
            mma16816(sc[2 * ntp + 1], qhr[kb8], kl[1], kl[3]);
        }

        // ---- causal mask (only near the diagonal) ----
        if (c * BN + 63 > grow0) {
            #pragma unroll
            for (int j = 0; j < 8; j++) {
                int gcol = c * BN + j * 8 + tg * 2;
                if (gcol     > grow0)     sc[j][0] = -INFINITY;
                if (gcol + 1 > grow0)     sc[j][1] = -INFINITY;
                if (gcol     > grow0 + 8) sc[j][2] = -INFINITY;
                if (gcol + 1 > grow0 + 8) sc[j][3] = -INFINITY;
            }
        }

        // ---- online softmax (warp-local; rows grp and grp+8) ----
        float mx0 = -INFINITY, mx1 = -INFINITY;
        #pragma unroll
        for (int j = 0; j < 8; j++) {
            mx0 = fmaxf(mx0, fmaxf(sc[j][0], sc[j][1]));
            mx1 = fmaxf(mx1, fmaxf(sc[j][2], sc[j][3]));
        }
        mx0 = fmaxf(mx0, __shfl_xor_sync(0xffffffffu, mx0, 1));
        mx0 = fmaxf(mx0, __shfl_xor_sync(0xffffffffu, mx0, 2));
        mx1 = fmaxf(mx1, __shfl_xor_sync(0xffffffffu, mx1, 1));
        mx1 = fmaxf(mx1, __shfl_xor_sync(0xffffffffu, mx1, 2));
        float mn0 = fmaxf(mA, mx0), mn1 = fmaxf(mB, mx1);
        float al0 = __expf(mA - mn0), al1 = __expf(mB - mn1);
        mA = mn0; mB = mn1;
        float s0 = 0.f, s1 = 0.f;
        #pragma unroll
        for (int j = 0; j < 8; j++) {
            sc[j][0] = __expf(sc[j][0] - mn0); s0 += sc[j][0];
            sc[j][1] = __expf(sc[j][1] - mn0); s0 += sc[j][1];
            sc[j][2] = __expf(sc[j][2] - mn1); s1 += sc[j][2];
            sc[j][3] = __expf(sc[j][3] - mn1); s1 += sc[j][3];
        }
        #pragma unroll
        for (int j = 0; j < 16; j++) {
            o_[j][0] *= al0; o_[j][1] *= al0;
            o_[j][2] *= al1; o_[j][3] *= al1;
        }

        // ---- O += P V  (P fp16; V single fp16 plane -> 1 MMA per n8 tile) ----
        #pragma unroll
        for (int s = 0; s < 4; s++) {
            uint32_t ph[4];
            ph[0] = packh2(sc[2 * s][0],     sc[2 * s][1]);
            ph[1] = packh2(sc[2 * s][2],     sc[2 * s][3]);
            ph[2] = packh2(sc[2 * s + 1][0], sc[2 * s + 1][1]);
            ph[3] = packh2(sc[2 * s + 1][2], sc[2 * s + 1][3]);
            int vr = s * 16 + l15;
            #pragma unroll
            for (int dp = 0; dp < 8; dp++) {
                uint32_t voff = swz(vr, dp * 2 + l16, 0);
                uint32_t vh[4];
                ldsm4t(vh, vb + voff);
                mma16816h(o_[2 * dp],     ph, vh[0], vh[1]);
                mma16816h(o_[2 * dp + 1], ph, vh[2], vh[3]);
            }
        }

        // ---- l-sum reduction off the critical path (after PV issue) ----
        s0 += __shfl_xor_sync(0xffffffffu, s0, 1);
        s0 += __shfl_xor_sync(0xffffffffu, s0, 2);
        s1 += __shfl_xor_sync(0xffffffffu, s1, 1);
        s1 += __shfl_xor_sync(0xffffffffu, s1, 2);
        lA = lA * al0 + s0;
        lB = lB * al1 + s1;
    }

    // ---- epilogue: normalize + store ----
    float inv0 = 1.0f / lA, inv1 = 1.0f / lB;
    float* r0 = ob + (size_t)(w * 16 + grp) * 128 + tg * 2;
    float* r1 = ob + (size_t)(w * 16 + grp + 8) * 128 + tg * 2;
    #pragma unroll
    for (int j = 0; j < 16; j++) {
        *(float2*)(r0 + j * 8) = make_float2(o_[j][0] * inv0, o_[j][1] * inv0);
        *(float2*)(r1 + j * 8) = make_float2(o_[j][2] * inv1, o_[j][3] * inv1);
    }
    cp_wait<0>();                            // drain (safety; none pending)
}

extern "C" void kernel_launch(void* const* d_in, const int* in_sizes, int n_in,
                              void* d_out, int out_size) {
    const float* q = (const float*)d_in[0];
    const float* k = (const float*)d_in[1];
    const float* v = (const float*)d_in[2];
    // d_in[3]: causal tril mask — semantics implemented directly.
    float* out = (float*)d_out;

    dim3 pgrid(NF4 / 256, 2);
    presplit_kernel<<<pgrid, 256>>>(k, v);

    cudaFuncSetAttribute(fa_mma_kernel,
                         cudaFuncAttributeMaxDynamicSharedMemorySize, SM_TOTAL);
    dim3 grid(SEQ / BM, NBH);
    fa_mma_kernel<<<grid, NTH, SM_TOTAL>>>(q, out);
}

// round 15
// speedup vs baseline: 1.0616x; 1.0115x over previous
#include <cuda_runtime.h>
#include <cuda_fp16.h>
#include <math.h>
#include <stdint.h>

#define NTH 128
#define BM 64
#define BN 64
#define NBH 32
#define SEQ 2048

// smem (per CTA, 96KB -> 2 CTAs/SM): K double-buffered (buf1 overlays the
// Q staging region, dead after Q-fragment preload); V fp16 double-buffered.
#define SM_K0HI 0
#define SM_K0LO 16384
#define SM_K1HI 32768
#define SM_K1LO 49152
#define SM_V0   65536
#define SM_V1   81920
#define SM_TOTAL 98304
#define SM_QHI SM_K1HI
#define SM_QLO SM_K1LO

#define NF4 (NBH * SEQ * 128 / 4)    // float4 count per tensor

// pre-split planes: K as bf16 hi/lo, V as fp16 (single plane)
__device__ __align__(16) uint2 gKhi[NF4];
__device__ __align__(16) uint2 gKlo[NF4];
__device__ __align__(16) uint2 gVh [NF4];

static __device__ __forceinline__ uint32_t s2u(const void* p) {
    return (uint32_t)__cvta_generic_to_shared((void*)p);
}

// split fp32 pair -> bf16x2 hi + bf16x2 lo (rn split; lo compensates hi)
static __device__ __forceinline__ void split2(float x, float y,
                                              uint32_t& hi, uint32_t& lo) {
    uint32_t h2;
    asm("cvt.rn.bf16x2.f32 %0, %1, %2;" : "=r"(h2) : "f"(y), "f"(x));
    float hx = __uint_as_float(h2 << 16);
    float hy = __uint_as_float(h2 & 0xffff0000u);
    float lx = x - hx, ly = y - hy;
    uint32_t l2;
    asm("cvt.rn.bf16x2.f32 %0, %1, %2;" : "=r"(l2) : "f"(ly), "f"(lx));
    hi = h2; lo = l2;
}

static __device__ __forceinline__ uint32_t packh2(float x, float y) {
    __half2 h = __float22half2_rn(make_float2(x, y));
    return *(uint32_t*)&h;
}

static __device__ __forceinline__ void ldsm4(uint32_t* r, uint32_t a) {
    asm volatile("ldmatrix.sync.aligned.m8n8.x4.shared.b16 {%0,%1,%2,%3}, [%4];"
                 : "=r"(r[0]), "=r"(r[1]), "=r"(r[2]), "=r"(r[3]) : "r"(a));
}
static __device__ __forceinline__ void ldsm4t(uint32_t* r, uint32_t a) {
    asm volatile("ldmatrix.sync.aligned.m8n8.x4.trans.shared.b16 {%0,%1,%2,%3}, [%4];"
                 : "=r"(r[0]), "=r"(r[1]), "=r"(r[2]), "=r"(r[3]) : "r"(a));
}

static __device__ __forceinline__ void mma16816(float* c, const uint32_t* a,
                                                uint32_t b0, uint32_t b1) {
    asm volatile(
        "mma.sync.aligned.m16n8k16.row.col.f32.bf16.bf16.f32 "
        "{%0,%1,%2,%3}, {%4,%5,%6,%7}, {%8,%9}, {%0,%1,%2,%3};"
        : "+f"(c[0]), "+f"(c[1]), "+f"(c[2]), "+f"(c[3])
        : "r"(a[0]), "r"(a[1]), "r"(a[2]), "r"(a[3]), "r"(b0), "r"(b1));
}

static __device__ __forceinline__ void mma16816h(float* c, const uint32_t* a,
                                                 uint32_t b0, uint32_t b1) {
    asm volatile(
        "mma.sync.aligned.m16n8k16.row.col.f32.f16.f16.f32 "
        "{%0,%1,%2,%3}, {%4,%5,%6,%7}, {%8,%9}, {%0,%1,%2,%3};"
        : "+f"(c[0]), "+f"(c[1]), "+f"(c[2]), "+f"(c[3])
        : "r"(a[0]), "r"(a[1]), "r"(a[2]), "r"(a[3]), "r"(b0), "r"(b1));
}

static __device__ __forceinline__ void cp16(uint32_t smem_dst, const void* gsrc) {
    asm volatile("cp.async.cg.shared.global [%0], [%1], 16;"
                 :: "r"(smem_dst), "l"(gsrc) : "memory");
}
static __device__ __forceinline__ void cp_commit() {
    asm volatile("cp.async.commit_group;" ::: "memory");
}
template <int N>
static __device__ __forceinline__ void cp_wait() {
    asm volatile("cp.async.wait_group %0;" :: "n"(N) : "memory");
}

// swizzled byte offset for (row, 16B-granule g, 8B half hb) in a 256B-row tile
static __device__ __forceinline__ uint32_t swz(int row, int g, int hb) {
    return (uint32_t)row * 256u + (uint32_t)((g ^ (row & 7)) << 4) + (uint32_t)hb * 8u;
}

// ---- pre-pass: split K (bf16 hi/lo) and V (fp16) once ----
__global__ __launch_bounds__(256, 8)
void presplit_kernel(const float* __restrict__ gk, const float* __restrict__ gv)
{
    int i = blockIdx.x * 256 + threadIdx.x;      // float4 index
    if (blockIdx.y == 0) {
        float4 x = ((const float4*)gk)[i];
        uint32_t h0, l0, h1, l1;
        split2(x.x, x.y, h0, l0);
        split2(x.z, x.w, h1, l1);
        gKhi[i] = make_uint2(h0, h1);
        gKlo[i] = make_uint2(l0, l1);
    } else {
        float4 x = ((const float4*)gv)[i];
        gVh[i] = make_uint2(packh2(x.x, x.y), packh2(x.z, x.w));
    }
}

__global__ __launch_bounds__(NTH, 2)
void fa_mma_kernel(const float* __restrict__ gq, float* __restrict__ go)
{
    extern __shared__ char smem[];
    const uint32_t sb = s2u(smem);
    const int tid = threadIdx.x;
    const int w   = tid >> 5, ln = tid & 31;
    const int grp = ln >> 2, tg = ln & 3;
    const int l15 = ln & 15, l16 = ln >> 4;
    const int qt  = (int)gridDim.x - 1 - (int)blockIdx.x;   // heavy CTAs first
    const int bh  = blockIdx.y;

    const float* qb = gq + ((size_t)bh * SEQ + (size_t)qt * BM) * 128;
    float*       ob = go + ((size_t)bh * SEQ + (size_t)qt * BM) * 128;
    const char* kbhi = (const char*)gKhi + (size_t)bh * SEQ * 256;
    const char* kblo = (const char*)gKlo + (size_t)bh * SEQ * 256;
    const char* vbh  = (const char*)gVh  + (size_t)bh * SEQ * 256;

    // ---- Q: load fp32, split to bf16 hi/lo into the K1 region (staging) ----
    #pragma unroll
    for (int i = 0; i < 16; i++) {
        int f = tid + i * NTH;               // float4 idx; row=f>>5, c4=f&31
        int r = f >> 5, c4 = f & 31;
        float4 qq = ((const float4*)qb)[f];
        uint32_t h0, l0, h1, l1;
        split2(qq.x, qq.y, h0, l0);
        split2(qq.z, qq.w, h1, l1);
        uint32_t off = swz(r, c4 >> 1, c4 & 1);
        *(uint2*)(smem + SM_QHI + off) = make_uint2(h0, h1);
        *(uint2*)(smem + SM_QLO + off) = make_uint2(l0, l1);
    }
    __syncthreads();

    const int nch = qt + 1;

    // ---- prologue: prefetch K(0) then V(0) as separate groups ----
    #pragma unroll
    for (int i = 0; i < 8; i++) {
        int f = tid + i * NTH;               // granule 0..1023
        int r = f >> 4, g = f & 15;
        uint32_t d = (uint32_t)r * 256u + (uint32_t)((g ^ (r & 7)) << 4);
        size_t s = (size_t)f * 16u;
        cp16(sb + SM_K0HI + d, kbhi + s);
        cp16(sb + SM_K0LO + d, kblo + s);
    }
    cp_commit();
    #pragma unroll
    for (int i = 0; i < 8; i++) {
        int f = tid + i * NTH;
        int r = f >> 4, g = f & 15;
        uint32_t d = (uint32_t)r * 256u + (uint32_t)((g ^ (r & 7)) << 4);
        size_t s = (size_t)f * 16u;
        cp16(sb + SM_V0 + d, vbh + s);
    }
    cp_commit();

    // ---- Q fragments -> registers (held for the whole kernel) ----
    const int qr = w * 16 + l15;
    const uint32_t qbaseH = sb + SM_QHI + qr * 256;
    const uint32_t qbaseL = sb + SM_QLO + qr * 256;
    const int qx = qr & 7;
    uint32_t qhr[8][4], qlr[8][4];
    #pragma unroll
    for (int kb8 = 0; kb8 < 8; kb8++) {
        uint32_t goff = (uint32_t)(((kb8 * 2 + l16) ^ qx) << 4);
        ldsm4(qhr[kb8], qbaseH + goff);
        ldsm4(qlr[kb8], qbaseL + goff);
    }
    __syncthreads();                         // Q region dead -> usable as K1

    float o_[16][4];
    #pragma unroll
    for (int j = 0; j < 16; j++)
        #pragma unroll
        for (int e = 0; e < 4; e++) o_[j][e] = 0.f;
    float mA = -INFINITY, mB = -INFINITY, lA = 0.f, lB = 0.f;

    const int grow0 = qt * BM + w * 16 + grp;    // global q-row of c0/c1

    for (int c = 0; c < nch; c++) {
        const int buf = c & 1;
        const uint32_t kb = sb + (buf ? SM_K1HI : SM_K0HI);
        const uint32_t vb = sb + (buf ? SM_V1   : SM_V0);

        cp_wait<1>();                        // K(c) landed (V(c) may be in flight)
        __syncthreads();                     // all warps done reading buffers c-1

        // ---- prefetch chunk c+1 (clamped; uniform group count) ----
        {
            int cc = (c + 1 <= qt) ? c + 1 : qt;
            const uint32_t kbn = sb + (buf ? SM_K0HI : SM_K1HI);
            const uint32_t vbn = sb + (buf ? SM_V0   : SM_V1);
            size_t tb = (size_t)cc * BN * 256;
            #pragma unroll
            for (int i = 0; i < 8; i++) {
                int f = tid + i * NTH;
                int r = f >> 4, g = f & 15;
                uint32_t d = (uint32_t)r * 256u + (uint32_t)((g ^ (r & 7)) << 4);
                size_t s = tb + (size_t)f * 16u;
                cp16(kbn + d, kbhi + s);
                cp16(kbn + 16384 + d, kblo + s);
            }
            cp_commit();
            #pragma unroll
            for (int i = 0; i < 8; i++) {
                int f = tid + i * NTH;
                int r = f >> 4, g = f & 15;
                uint32_t d = (uint32_t)r * 256u + (uint32_t)((g ^ (r & 7)) << 4);
                size_t s = tb + (size_t)f * 16u;
                cp16(vbn + d, vbh + s);
            }
            cp_commit();
        }

        // ---- S = Q K^T  (3-way bf16 split; K frags ping-pong pipelined) ----
        float sc[8][4];
        #pragma unroll
        for (int j = 0; j < 8; j++)
            #pragma unroll
            for (int e = 0; e < 4; e++) sc[j][e] = 0.f;

        uint32_t kf[2][2][4];                // [pingpong][hi/lo][frag]
        {
            uint32_t koff0 = swz(l15, l16, 0);   // it=0: ntp=0, kb8=0
            ldsm4(kf[0][0], kb + koff0);
            ldsm4(kf[0][1], kb + 16384 + koff0);
        }
        #pragma unroll
        for (int it = 0; it < 32; it++) {    // it = kb8*4 + ntp
            const int cur = it & 1, nxt = cur ^ 1;
            if (it < 31) {
                const int it1 = it + 1;
                uint32_t koff = swz((it1 & 3) * 16 + l15,
                                    (it1 >> 2) * 2 + l16, 0);
                ldsm4(kf[nxt][0], kb + koff);
                ldsm4(kf[nxt][1], kb + 16384 + koff);
            }
            const int ntp = it & 3, kb8 = it >> 2;
            const uint32_t* kh = kf[cur][0];
            const uint32_t* kl = kf[cur][1];
            mma16816(sc[2 * ntp],     qhr[kb8], kh[0], kh[2]);
            mma16816(sc[2 * ntp],     qlr[kb8], kh[0], kh[2]);
            mma16816(sc[2 * ntp],     qhr[kb8], kl[0], kl[2]);
            mma16816(sc[2 * ntp + 1], qhr[kb8], kh[1], kh[3]);
            mma16816(sc[2 * ntp + 1], qlr[kb8], kh[1], kh[3]);
            mma16816(sc[2 * ntp + 1], qhr[kb8], kl[1], kl[3]);
        }

        // ---- causal mask (only near the diagonal) ----
        if (c * BN + 63 > grow0) {
            #pragma unroll
            for (int j = 0; j < 8; j++) {
                int gcol = c * BN + j * 8 + tg * 2;
                if (gcol     > grow0)     sc[j][0] = -INFINITY;
                if (gcol + 1 > grow0)     sc[j][1] = -INFINITY;
                if (gcol     > grow0 + 8) sc[j][2] = -INFINITY;
                if (gcol + 1 > grow0 + 8) sc[j][3] = -INFINITY;
            }
        }

        // ---- online softmax (warp-local; rows grp and grp+8) ----
        float mx0 = -INFINITY, mx1 = -INFINITY;
        #pragma unroll
        for (int j = 0; j < 8; j++) {
            mx0 = fmaxf(mx0, fmaxf(sc[j][0], sc[j][1]));
            mx1 = fmaxf(mx1, fmaxf(sc[j][2], sc[j][3]));
        }
        mx0 = fmaxf(mx0, __shfl_xor_sync(0xffffffffu, mx0, 1));
        mx0 = fmaxf(mx0, __shfl_xor_sync(0xffffffffu, mx0, 2));
        mx1 = fmaxf(mx1, __shfl_xor_sync(0xffffffffu, mx1, 1));
        mx1 = fmaxf(mx1, __shfl_xor_sync(0xffffffffu, mx1, 2));
        float mn0 = fmaxf(mA, mx0), mn1 = fmaxf(mB, mx1);
        float al0 = __expf(mA - mn0), al1 = __expf(mB - mn1);
        mA = mn0; mB = mn1;
        float s0 = 0.f, s1 = 0.f;
        #pragma unroll
        for (int j = 0; j < 8; j++) {
            sc[j][0] = __expf(sc[j][0] - mn0); s0 += sc[j][0];
            sc[j][1] = __expf(sc[j][1] - mn0); s0 += sc[j][1];
            sc[j][2] = __expf(sc[j][2] - mn1); s1 += sc[j][2];
            sc[j][3] = __expf(sc[j][3] - mn1); s1 += sc[j][3];
        }
        #pragma unroll
        for (int j = 0; j < 16; j++) {
            o_[j][0] *= al0; o_[j][1] *= al0;
            o_[j][2] *= al1; o_[j][3] *= al1;
        }

        cp_wait<2>();                        // V(c) landed (c+1 groups in flight)

        // ---- O += P V  (V frags ping-pong pipelined; P fp16 single term) ----
        {
            uint32_t vf[2][4];               // [pingpong][frag]
            ldsm4t(vf[0], vb + swz(l15, l16, 0));    // it=0: s=0, dp=0
            uint32_t ph[4];
            #pragma unroll
            for (int it = 0; it < 32; it++) {        // it = s*8 + dp
                const int s = it >> 3, dp = it & 7;
                const int cur = it & 1, nxt = cur ^ 1;
                if ((it & 7) == 0) {
                    ph[0] = packh2(sc[2 * s][0],     sc[2 * s][1]);
                    ph[1] = packh2(sc[2 * s][2],     sc[2 * s][3]);
                    ph[2] = packh2(sc[2 * s + 1][0], sc[2 * s + 1][1]);
                    ph[3] = packh2(sc[2 * s + 1][2], sc[2 * s + 1][3]);
                }
                if (it < 31) {
                    const int it1 = it + 1;
                    uint32_t voff = swz((it1 >> 3) * 16 + l15,
                                        (it1 & 7) * 2 + l16, 0);
                    ldsm4t(vf[nxt], vb + voff);
                }
                mma16816h(o_[2 * dp],     ph, vf[cur][0], vf[cur][1]);
                mma16816h(o_[2 * dp + 1], ph, vf[cur][2], vf[cur][3]);
            }
        }

        // ---- l-sum reduction off the critical path (after PV issue) ----
        s0 += __shfl_xor_sync(0xffffffffu, s0, 1);
        s0 += __shfl_xor_sync(0xffffffffu, s0, 2);
        s1 += __shfl_xor_sync(0xffffffffu, s1, 1);
        s1 += __shfl_xor_sync(0xffffffffu, s1, 2);
        lA = lA * al0 + s0;
        lB = lB * al1 + s1;
    }

    // ---- epilogue: normalize + store ----
    float inv0 = 1.0f / lA, inv1 = 1.0f / lB;
    float* r0 = ob + (size_t)(w * 16 + grp) * 128 + tg * 2;
    float* r1 = ob + (size_t)(w * 16 + grp + 8) * 128 + tg * 2;
    #pragma unroll
    for (int j = 0; j < 16; j++) {
        *(float2*)(r0 + j * 8) = make_float2(o_[j][0] * inv0, o_[j][1] * inv0);
        *(float2*)(r1 + j * 8) = make_float2(o_[j][2] * inv1, o_[j][3] * inv1);
    }
    cp_wait<0>();                            // drain trailing prefetches
}

extern "C" void kernel_launch(void* const* d_in, const int* in_sizes, int n_in,
                              void* d_out, int out_size) {
    const float* q = (const float*)d_in[0];
    const float* k = (const float*)d_in[1];
    const float* v = (const float*)d_in[2];
    // d_in[3]: causal tril mask — semantics implemented directly.
    float* out = (float*)d_out;

    dim3 pgrid(NF4 / 256, 2);
    presplit_kernel<<<pgrid, 256>>>(k, v);

    cudaFuncSetAttribute(fa_mma_kernel,
                         cudaFuncAttributeMaxDynamicSharedMemorySize, SM_TOTAL);
    dim3 grid(SEQ / BM, NBH);
    fa_mma_kernel<<<grid, NTH, SM_TOTAL>>>(q, out);
}